// round 14
// baseline (speedup 1.0000x reference)
#include <cuda_runtime.h>
#include <cuda_bf16.h>
#include <math_constants.h>
#include <cstdint>

// Problem constants
constexpr int B_  = 4;
constexpr int L_  = 2048;
constexpr int D_  = 1024;
constexpr int H_  = 16;
constexpr int HD_ = 64;
constexpr int M_  = B_ * L_;       // 8192
constexpr int QKV_N = 3 * D_;      // 3072

// ---------------------------------------------------------------------------
// Scratch (allocation-free -> __device__ globals)
// ---------------------------------------------------------------------------
__device__ __nv_bfloat16 g_xhi[(size_t)M_ * D_];
__device__ __nv_bfloat16 g_xlo[(size_t)M_ * D_];
__device__ __nv_bfloat16 g_qkvh[(size_t)M_ * QKV_N];
__device__ __nv_bfloat16 g_qkvl[(size_t)M_ * QKV_N];
__device__ __nv_bfloat16 g_ahi[(size_t)M_ * D_];
__device__ __nv_bfloat16 g_alo[(size_t)M_ * D_];
__device__ __nv_bfloat16 g_wqh[(size_t)QKV_N * D_];
__device__ __nv_bfloat16 g_wql[(size_t)QKV_N * D_];
__device__ __nv_bfloat16 g_wph[(size_t)D_ * D_];
__device__ __nv_bfloat16 g_wpl[(size_t)D_ * D_];

// ---------------------------------------------------------------------------
// PTX helpers
// ---------------------------------------------------------------------------
__device__ __forceinline__ uint32_t smem_u32(const void* p) {
    uint32_t a;
    asm("{ .reg .u64 t; cvta.to.shared.u64 t, %1; cvt.u32.u64 %0, t; }"
        : "=r"(a) : "l"(p));
    return a;
}
__device__ __forceinline__ void cpasync16(uint32_t saddr, const void* g) {
    asm volatile("cp.async.cg.shared.global [%0], [%1], 16;" :: "r"(saddr), "l"(g));
}
#define CP_COMMIT() asm volatile("cp.async.commit_group;" ::: "memory")
#define CP_WAIT(n)  asm volatile("cp.async.wait_group %0;" :: "n"(n) : "memory")

__device__ __forceinline__ void ldm_x4(uint32_t* r, uint32_t addr) {
    asm volatile("ldmatrix.sync.aligned.m8n8.x4.shared.b16 {%0,%1,%2,%3}, [%4];"
                 : "=r"(r[0]), "=r"(r[1]), "=r"(r[2]), "=r"(r[3]) : "r"(addr));
}
__device__ __forceinline__ void ldm_x4_t(uint32_t* r, uint32_t addr) {
    asm volatile("ldmatrix.sync.aligned.m8n8.x4.trans.shared.b16 {%0,%1,%2,%3}, [%4];"
                 : "=r"(r[0]), "=r"(r[1]), "=r"(r[2]), "=r"(r[3]) : "r"(addr));
}
__device__ __forceinline__ void mma_bf16(float* c, const uint32_t* a,
                                         const uint32_t* b) {
    asm("mma.sync.aligned.m16n8k16.row.col.f32.bf16.bf16.f32 "
        "{%0,%1,%2,%3},{%4,%5,%6,%7},{%8,%9},{%0,%1,%2,%3};"
        : "+f"(c[0]), "+f"(c[1]), "+f"(c[2]), "+f"(c[3])
        : "r"(a[0]), "r"(a[1]), "r"(a[2]), "r"(a[3]), "r"(b[0]), "r"(b[1]));
}
__device__ __forceinline__ void pack_hilo(float x, float y,
                                          uint32_t& hi, uint32_t& lo) {
    __nv_bfloat162 h2 = __floats2bfloat162_rn(x, y);
    float2 f2 = __bfloat1622float2(h2);
    __nv_bfloat162 l2 = __floats2bfloat162_rn(x - f2.x, y - f2.y);
    hi = *(uint32_t*)&h2;
    lo = *(uint32_t*)&l2;
}

// ---------------------------------------------------------------------------
// Split kernels
// ---------------------------------------------------------------------------
__global__ void split_a_kernel(const float* __restrict__ A,
                               __nv_bfloat16* __restrict__ Ah,
                               __nv_bfloat16* __restrict__ Al, int n4)
{
    int i = blockIdx.x * blockDim.x + threadIdx.x;
    if (i >= n4) return;
    float4 v = ((const float4*)A)[i];
    uint32_t h0, l0, h1, l1;
    pack_hilo(v.x, v.y, h0, l0);
    pack_hilo(v.z, v.w, h1, l1);
    ((uint32_t*)Ah)[2 * i]     = h0;
    ((uint32_t*)Ah)[2 * i + 1] = h1;
    ((uint32_t*)Al)[2 * i]     = l0;
    ((uint32_t*)Al)[2 * i + 1] = l1;
}

__global__ void split_wT_kernel(const float* __restrict__ W,
                                __nv_bfloat16* __restrict__ Bh,
                                __nv_bfloat16* __restrict__ Bl, int K, int N)
{
    __shared__ float t[32][33];
    const int bx = blockIdx.x, by = blockIdx.y;
    const int tx = threadIdx.x, ty = threadIdx.y;
#pragma unroll
    for (int i = 0; i < 4; i++) {
        int k = by * 32 + ty + i * 8;
        t[ty + i * 8][tx] = W[(size_t)k * N + bx * 32 + tx];
    }
    __syncthreads();
#pragma unroll
    for (int i = 0; i < 4; i++) {
        int n = bx * 32 + ty + i * 8;
        int k = by * 32 + tx;
        float v = t[tx][ty + i * 8];
        __nv_bfloat16 h = __float2bfloat16_rn(v);
        Bh[(size_t)n * K + k] = h;
        Bl[(size_t)n * K + k] = __float2bfloat16_rn(v - __bfloat162float(h));
    }
}

// ---------------------------------------------------------------------------
// HMMA split-bf16 GEMM (unchanged from round 10/13 proven state).
// ---------------------------------------------------------------------------
constexpr int GBH = 128 * 80;
constexpr int GBL = 128 * 64;
constexpr int GSTAGE = 2 * GBH + 2 * GBL;  // 36864
constexpr size_t GM_SMEM = 3 * GSTAGE;     // 110592 B

template <bool SPLIT_OUT>
__global__ void __launch_bounds__(256, 2) gemm_mma_kernel(
    const __nv_bfloat16* __restrict__ Ah, const __nv_bfloat16* __restrict__ Al,
    const __nv_bfloat16* __restrict__ Bh, const __nv_bfloat16* __restrict__ Bl,
    const float* __restrict__ bias, float* __restrict__ C,
    __nv_bfloat16* __restrict__ Ch, __nv_bfloat16* __restrict__ Cl,
    int N, int K)
{
    extern __shared__ char smem[];
    const uint32_t sb = smem_u32(smem);
    const int tid  = threadIdx.x;
    const int wid  = tid >> 5;
    const int lane = tid & 31;
    const int warp_m = wid >> 2;
    const int warp_n = wid & 3;
    const int row0 = blockIdx.y * 128;
    const int col0 = blockIdx.x * 128;

    float acc[4][4][4];
#pragma unroll
    for (int mt = 0; mt < 4; mt++)
#pragma unroll
        for (int nt = 0; nt < 4; nt++)
#pragma unroll
            for (int q = 0; q < 4; q++) acc[mt][nt][q] = 0.f;

    const int nChunks = K >> 5;
    const int lr0 = tid >> 2;
    const int lch = tid & 3;

    auto load_stage = [&](int s, int c) {
        const int k0 = c << 5;
        const uint32_t st = sb + s * GSTAGE;
#pragma unroll
        for (int i = 0; i < 2; i++) {
            const int r = lr0 + i * 64;
            const uint32_t so_h = r * 80 + lch * 16;
            const uint32_t so_l = r * 64 + ((lch ^ ((r >> 1) & 3)) << 4);
            const size_t ga = (size_t)(row0 + r) * K + k0 + lch * 8;
            const size_t gb = (size_t)(col0 + r) * K + k0 + lch * 8;
            cpasync16(st + so_h, Ah + ga);
            cpasync16(st + GBH + so_h, Bh + gb);
            cpasync16(st + 2 * GBH + so_l, Al + ga);
            cpasync16(st + 2 * GBH + GBL + so_l, Bl + gb);
        }
    };
    auto load_slot = [&](int s, int c2, int slot) {
        const int k0 = c2 << 5;
        const uint32_t st = sb + s * GSTAGE;
        const int i = slot >> 2;
        const int which = slot & 3;
        const int r = lr0 + i * 64;
        const uint32_t so_h = r * 80 + lch * 16;
        const uint32_t so_l = r * 64 + ((lch ^ ((r >> 1) & 3)) << 4);
        if (which == 0)
            cpasync16(st + so_h, Ah + (size_t)(row0 + r) * K + k0 + lch * 8);
        else if (which == 1)
            cpasync16(st + GBH + so_h, Bh + (size_t)(col0 + r) * K + k0 + lch * 8);
        else if (which == 2)
            cpasync16(st + 2 * GBH + so_l, Al + (size_t)(row0 + r) * K + k0 + lch * 8);
        else
            cpasync16(st + 2 * GBH + GBL + so_l,
                      Bl + (size_t)(col0 + r) * K + k0 + lch * 8);
    };

    load_stage(0, 0);
    CP_COMMIT();
    load_stage(1, 1);
    CP_COMMIT();

    const int arow  = warp_m * 64 + (lane & 15);
    const int acolb = ((lane >> 4) & 1) * 16;
    const int ahalf = (lane >> 4) & 1;
    const int bnrow = warp_n * 32 + (lane & 7) + ((lane >> 4) & 1) * 8;
    const int bcolb = ((lane >> 3) & 1) * 16;
    const int bhalf = (lane >> 3) & 1;

    int cur = 0, ldb = 2;
    for (int c = 0; c < nChunks; c++) {
        if (c + 1 < nChunks) { CP_WAIT(1); } else { CP_WAIT(0); }
        __syncthreads();
        const bool doLoad = (c + 2 < nChunks);

        const uint32_t st  = sb + cur * GSTAGE;
        const uint32_t sAh = st;
        const uint32_t sBh = st + GBH;
        const uint32_t sAl = st + 2 * GBH;
        const uint32_t sBl = st + 2 * GBH + GBL;

        auto ldA = [&](uint32_t* h, uint32_t* l, int ks, int mt) {
            const int rA = arow + mt * 16;
            const uint32_t roh = (uint32_t)rA * 80 + acolb + ks * 32;
            const int cA = ks * 2 + ahalf;
            const uint32_t rol = (uint32_t)rA * 64 +
                                 ((cA ^ ((rA >> 1) & 3)) << 4);
            ldm_x4(h, sAh + roh);
            ldm_x4(l, sAl + rol);
        };

        uint32_t aH[2][4], aL[2][4];
        ldA(aH[0], aL[0], 0, 0);

#pragma unroll
        for (int ks = 0; ks < 2; ks++) {
            const int kb = ks * 32;
            uint32_t bh[4][2], bl[4][2];
#pragma unroll
            for (int np = 0; np < 2; np++) {
                const int rB = bnrow + np * 16;
                const uint32_t roh = (uint32_t)rB * 80 + bcolb + kb;
                const int cB = ks * 2 + bhalf;
                const uint32_t rol = (uint32_t)rB * 64 +
                                     ((cB ^ ((rB >> 1) & 3)) << 4);
                uint32_t t0[4], t1[4];
                ldm_x4(t0, sBh + roh);
                ldm_x4(t1, sBl + rol);
                bh[2 * np][0] = t0[0]; bh[2 * np][1] = t0[1];
                bh[2 * np + 1][0] = t0[2]; bh[2 * np + 1][1] = t0[3];
                bl[2 * np][0] = t1[0]; bl[2 * np][1] = t1[1];
                bl[2 * np + 1][0] = t1[2]; bl[2 * np + 1][1] = t1[3];
            }
#pragma unroll
            for (int mt = 0; mt < 4; mt++) {
                const int slot = ks * 4 + mt;
                if (doLoad) load_slot(ldb, c + 2, slot);
                if (slot < 7) {
                    const int ns = slot + 1;
                    ldA(aH[ns & 1], aL[ns & 1], ns >> 2, ns & 3);
                }
                const uint32_t* ah = aH[slot & 1];
                const uint32_t* al = aL[slot & 1];
#pragma unroll
                for (int nt = 0; nt < 4; nt++)
                    mma_bf16(acc[mt][nt], ah, bh[nt]);
#pragma unroll
                for (int nt = 0; nt < 4; nt++)
                    mma_bf16(acc[mt][nt], ah, bl[nt]);
#pragma unroll
                for (int nt = 0; nt < 4; nt++)
                    mma_bf16(acc[mt][nt], al, bh[nt]);
            }
        }
        if (doLoad) CP_COMMIT();
        cur = (cur == 2) ? 0 : cur + 1;
        ldb = (ldb == 2) ? 0 : ldb + 1;
    }

    const int g  = lane >> 2;
    const int tc = (lane & 3) * 2;
#pragma unroll
    for (int nt = 0; nt < 4; nt++) {
        const int cg = col0 + warp_n * 32 + nt * 8 + tc;
        const float bx = bias[cg];
        const float by = bias[cg + 1];
#pragma unroll
        for (int mt = 0; mt < 4; mt++) {
            const int rg = row0 + warp_m * 64 + mt * 16 + g;
            float v00 = acc[mt][nt][0] + bx, v01 = acc[mt][nt][1] + by;
            float v10 = acc[mt][nt][2] + bx, v11 = acc[mt][nt][3] + by;
            if (SPLIT_OUT) {
                uint32_t h0, l0, h1, l1;
                pack_hilo(v00, v01, h0, l0);
                pack_hilo(v10, v11, h1, l1);
                *(uint32_t*)(Ch + (size_t)rg * N + cg)       = h0;
                *(uint32_t*)(Cl + (size_t)rg * N + cg)       = l0;
                *(uint32_t*)(Ch + (size_t)(rg + 8) * N + cg) = h1;
                *(uint32_t*)(Cl + (size_t)(rg + 8) * N + cg) = l1;
            } else {
                float2 a0; a0.x = v00; a0.y = v01;
                float2 a1; a1.x = v10; a1.y = v11;
                *(float2*)(C + (size_t)rg * N + cg)       = a0;
                *(float2*)(C + (size_t)(rg + 8) * N + cg) = a1;
            }
        }
    }
}

// ---------------------------------------------------------------------------
// Tensor-core flash attention (causal). CTA = 128 q-rows x (b,h). 8 warps.
// R14: DEFERRED PV — at iteration kt: S(kt) MMAs, then softmax(kt) (MUFU)
// with the independent [O*=a_prev; O += P(kt-1)V(kt-1)] MMA block adjacent so
// MUFU hides under tensor work. 4-stage K/V pipeline (V(kt-1) must outlive
// loads for kt+2). LPT scheduling + spread loads retained.
// ---------------------------------------------------------------------------
constexpr int APB      = 144;
constexpr int AT_QB    = 128 * APB;         // 18432
constexpr int AT_KVT   = 64 * APB;          // 9216
constexpr int AT_STAGE = 4 * AT_KVT;        // 36864
constexpr size_t AT_SMEM = 2 * (size_t)AT_QB + 4 * (size_t)AT_STAGE;  // 184320

__global__ void __launch_bounds__(256, 1) attn_mma_kernel(
    const __nv_bfloat16* __restrict__ qkvh,
    const __nv_bfloat16* __restrict__ qkvl,
    __nv_bfloat16* __restrict__ outh,
    __nv_bfloat16* __restrict__ outl)
{
    extern __shared__ char smem[];
    const uint32_t sb = smem_u32(smem);
    const uint32_t sQh = sb;
    const uint32_t sQl = sb + AT_QB;
    const uint32_t sS0 = sb + 2 * AT_QB;

    const int qb = (int)gridDim.x - 1 - (int)blockIdx.x;  // LPT: heavy first
    const int h  = blockIdx.y;
    const int b  = blockIdx.z;
    const int tid  = threadIdx.x;
    const int wid  = tid >> 5;
    const int lane = tid & 31;

    const size_t qrow0 = (size_t)(b * L_ + qb * 128);

    // ---- Q hi/lo -> smem ----
#pragma unroll
    for (int i = 0; i < 4; i++) {
        const int id = i * 256 + tid;
        const int r = id >> 3, s = id & 7;
        const size_t g = (qrow0 + r) * QKV_N + h * HD_ + s * 8;
        const uint32_t so = r * APB + s * 16;
        cpasync16(sQh + so, qkvh + g);
        cpasync16(sQl + so, qkvl + g);
    }
    CP_COMMIT();

    const int nkt = 2 * qb + 2;

    auto load_kv = [&](int buf, int kt) {
        const uint32_t st = sS0 + buf * AT_STAGE;
        const size_t krow0 = (size_t)(b * L_ + kt * 64);
#pragma unroll
        for (int i = 0; i < 2; i++) {
            const int id = i * 256 + tid;
            const int r = id >> 3, s = id & 7;
            const size_t gk = (krow0 + r) * QKV_N + D_ + h * HD_ + s * 8;
            const size_t gv = gk + D_;
            const uint32_t so = r * APB + s * 16;
            cpasync16(st + 0 * AT_KVT + so, qkvh + gk);
            cpasync16(st + 1 * AT_KVT + so, qkvl + gk);
            cpasync16(st + 2 * AT_KVT + so, qkvh + gv);
            cpasync16(st + 3 * AT_KVT + so, qkvl + gv);
        }
    };
    auto load_kv_slot = [&](int buf, int kt, int slot) {
        const uint32_t st = sS0 + buf * AT_STAGE;
        const size_t krow0 = (size_t)(b * L_ + kt * 64);
        const int i = slot >> 2;
        const int which = slot & 3;
        const int id = i * 256 + tid;
        const int r = id >> 3, s = id & 7;
        const size_t gk = (krow0 + r) * QKV_N + D_ + h * HD_ + s * 8;
        const uint32_t so = r * APB + s * 16;
        if (which == 0)      cpasync16(st + 0 * AT_KVT + so, qkvh + gk);
        else if (which == 1) cpasync16(st + 1 * AT_KVT + so, qkvl + gk);
        else if (which == 2) cpasync16(st + 2 * AT_KVT + so, qkvh + gk + D_);
        else                 cpasync16(st + 3 * AT_KVT + so, qkvl + gk + D_);
    };

    load_kv(0, 0);
    CP_COMMIT();
    load_kv(1, 1);
    CP_COMMIT();

    CP_WAIT(2);
    __syncthreads();
    uint32_t qh[4][4], ql[4][4];
    {
        const uint32_t base = (uint32_t)(wid * 16 + (lane & 15)) * APB +
                              ((lane >> 4) & 1) * 16;
#pragma unroll
        for (int j = 0; j < 4; j++) {
            ldm_x4(qh[j], sQh + base + j * 32);
            ldm_x4(ql[j], sQl + base + j * 32);
        }
    }

    float o[8][4];
#pragma unroll
    for (int nt = 0; nt < 8; nt++)
#pragma unroll
        for (int q = 0; q < 4; q++) o[nt][q] = 0.f;
    float m0 = -CUDART_INF_F, m1 = -CUDART_INF_F;
    float l0 = 0.f, l1 = 0.f;

    const int row_r0 = qb * 128 + wid * 16 + (lane >> 2);
    const int ccol   = 2 * (lane & 3);
    constexpr float SCALE = 0.125f;
    constexpr float LOG2E = 1.44269504f;

    const uint32_t kbase = (uint32_t)((lane & 7) + ((lane >> 4) & 1) * 8) * APB +
                           ((lane >> 3) & 1) * 16;
    const int vmat = lane >> 3;
    const uint32_t vrowb = (uint32_t)((vmat & 1) * 8 + (lane & 7)) * APB +
                           (vmat >> 1) * 16;

    // deferred-PV state
    uint32_t ph[4][4], pl[4][4];    // P(kt-1) fragments
    float a0p = 1.f, a1p = 1.f;     // a(kt-1)

    // PV block: O = O*a + P_prev * V(stage vst)  (slot-pipelined V fragments)
    auto do_pv = [&](uint32_t vst, float A0, float A1) {
        const uint32_t sVh = vst + 2 * AT_KVT;
        const uint32_t sVl = vst + 3 * AT_KVT;
        uint32_t vfh[2][2][2], vfl[2][2][2];
        auto ldV = [&](int buf, int j, int pp) {
            const uint32_t ro = vrowb + (uint32_t)(j * 16) * APB + pp * 32;
            uint32_t t0[4], t1[4];
            ldm_x4_t(t0, sVh + ro);
            ldm_x4_t(t1, sVl + ro);
            vfh[buf][0][0] = t0[0]; vfh[buf][0][1] = t0[1];
            vfh[buf][1][0] = t0[2]; vfh[buf][1][1] = t0[3];
            vfl[buf][0][0] = t1[0]; vfl[buf][0][1] = t1[1];
            vfl[buf][1][0] = t1[2]; vfl[buf][1][1] = t1[3];
        };
        ldV(0, 0, 0);
#pragma unroll
        for (int nt = 0; nt < 8; nt++) {
            o[nt][0] *= A0; o[nt][1] *= A0;
            o[nt][2] *= A1; o[nt][3] *= A1;
        }
#pragma unroll
        for (int j = 0; j < 4; j++) {
#pragma unroll
            for (int pp = 0; pp < 4; pp++) {
                const int slot = j * 4 + pp;
                const int cb = slot & 1;
                if (slot < 15) ldV(cb ^ 1, (slot + 1) >> 2, (slot + 1) & 3);
#pragma unroll
                for (int t = 0; t < 2; t++) {
                    const int nt = 2 * pp + t;
                    mma_bf16(o[nt], ph[j], vfh[cb][t]);
                    mma_bf16(o[nt], ph[j], vfl[cb][t]);
                    mma_bf16(o[nt], pl[j], vfh[cb][t]);
                }
            }
        }
    };

    int cur = 0, ldb = 2, prevcur = 0;
    for (int kt = 0; kt < nkt; kt++) {
        if (kt + 1 < nkt) { CP_WAIT(1); } else { CP_WAIT(0); }
        __syncthreads();
        const bool doLoad = (kt + 2 < nkt);

        const uint32_t st  = sS0 + cur * AT_STAGE;
        const uint32_t sKh = st;
        const uint32_t sKl = st + AT_KVT;

        // ---- S = Q K^T (slot-pipelined; spread cp.async over slots 0..7) ----
        float s[8][4];
#pragma unroll
        for (int nt = 0; nt < 8; nt++)
#pragma unroll
            for (int q = 0; q < 4; q++) s[nt][q] = 0.f;

        uint32_t kfh[2][2][2], kfl[2][2][2];
        auto ldK = [&](int buf, int j, int np) {
            const uint32_t ro = kbase + (uint32_t)(np * 16) * APB + j * 32;
            uint32_t t0[4], t1[4];
            ldm_x4(t0, sKh + ro);
            ldm_x4(t1, sKl + ro);
            kfh[buf][0][0] = t0[0]; kfh[buf][0][1] = t0[1];
            kfh[buf][1][0] = t0[2]; kfh[buf][1][1] = t0[3];
            kfl[buf][0][0] = t1[0]; kfl[buf][0][1] = t1[1];
            kfl[buf][1][0] = t1[2]; kfl[buf][1][1] = t1[3];
        };
        ldK(0, 0, 0);
#pragma unroll
        for (int j = 0; j < 4; j++) {
#pragma unroll
            for (int np = 0; np < 4; np++) {
                const int slot = j * 4 + np;
                const int cb = slot & 1;
                if (doLoad && slot < 8) load_kv_slot(ldb, kt + 2, slot);
                if (slot < 15) ldK(cb ^ 1, (slot + 1) >> 2, (slot + 1) & 3);
#pragma unroll
                for (int t = 0; t < 2; t++) {
                    const int nt = 2 * np + t;
                    mma_bf16(s[nt], qh[j], kfh[cb][t]);
                    mma_bf16(s[nt], qh[j], kfl[cb][t]);
                    mma_bf16(s[nt], ql[j], kfh[cb][t]);
                }
            }
        }
        if (doLoad) CP_COMMIT();

        // ---- softmax(kt): scale, mask, max, exps (MUFU) ----
#pragma unroll
        for (int nt = 0; nt < 8; nt++)
#pragma unroll
            for (int q = 0; q < 4; q++) s[nt][q] *= SCALE;

        if (kt >= 2 * qb) {
#pragma unroll
            for (int nt = 0; nt < 8; nt++) {
                const int col = kt * 64 + nt * 8 + ccol;
                if (col > row_r0)         s[nt][0] = -CUDART_INF_F;
                if (col + 1 > row_r0)     s[nt][1] = -CUDART_INF_F;
                if (col > row_r0 + 8)     s[nt][2] = -CUDART_INF_F;
                if (col + 1 > row_r0 + 8) s[nt][3] = -CUDART_INF_F;
            }
        }

        float tm0 = -CUDART_INF_F, tm1 = -CUDART_INF_F;
#pragma unroll
        for (int nt = 0; nt < 8; nt++) {
            tm0 = fmaxf(tm0, fmaxf(s[nt][0], s[nt][1]));
            tm1 = fmaxf(tm1, fmaxf(s[nt][2], s[nt][3]));
        }
        tm0 = fmaxf(tm0, __shfl_xor_sync(0xffffffffu, tm0, 1));
        tm0 = fmaxf(tm0, __shfl_xor_sync(0xffffffffu, tm0, 2));
        tm1 = fmaxf(tm1, __shfl_xor_sync(0xffffffffu, tm1, 1));
        tm1 = fmaxf(tm1, __shfl_xor_sync(0xffffffffu, tm1, 2));

        const float mn0 = fmaxf(m0, tm0);
        const float mn1 = fmaxf(m1, tm1);
        const float a0 = exp2f((m0 - mn0) * LOG2E);
        const float a1 = exp2f((m1 - mn1) * LOG2E);
        m0 = mn0; m1 = mn1;

        float rs0 = 0.f, rs1 = 0.f;
#pragma unroll
        for (int nt = 0; nt < 8; nt++) {
            float p0 = exp2f((s[nt][0] - mn0) * LOG2E);
            float p1 = exp2f((s[nt][1] - mn0) * LOG2E);
            float p2 = exp2f((s[nt][2] - mn1) * LOG2E);
            float p3 = exp2f((s[nt][3] - mn1) * LOG2E);
            s[nt][0] = p0; s[nt][1] = p1; s[nt][2] = p2; s[nt][3] = p3;
            rs0 += p0 + p1;
            rs1 += p2 + p3;
        }
        rs0 += __shfl_xor_sync(0xffffffffu, rs0, 1);
        rs0 += __shfl_xor_sync(0xffffffffu, rs0, 2);
        rs1 += __shfl_xor_sync(0xffffffffu, rs1, 1);
        rs1 += __shfl_xor_sync(0xffffffffu, rs1, 2);
        l0 = a0 * l0 + rs0;
        l1 = a1 * l1 + rs1;

        // ---- deferred PV(kt-1): independent MMA block — MUFU above can
        //      be interleaved with these tensor ops by the scheduler ----
        if (kt > 0)
            do_pv(sS0 + prevcur * AT_STAGE, a0p, a1p);

        // ---- pack P(kt) -> ph/pl (prev-state for next iteration) ----
#pragma unroll
        for (int j = 0; j < 4; j++) {
            pack_hilo(s[2 * j][0],     s[2 * j][1],     ph[j][0], pl[j][0]);
            pack_hilo(s[2 * j][2],     s[2 * j][3],     ph[j][1], pl[j][1]);
            pack_hilo(s[2 * j + 1][0], s[2 * j + 1][1], ph[j][2], pl[j][2]);
            pack_hilo(s[2 * j + 1][2], s[2 * j + 1][3], ph[j][3], pl[j][3]);
        }
        a0p = a0;
        a1p = a1;

        prevcur = cur;
        cur = (cur + 1) & 3;
        ldb = (ldb + 1) & 3;
    }

    // ---- epilogue PV for the final tile ----
    do_pv(sS0 + prevcur * AT_STAGE, a0p, a1p);

    // ---- finalize: /l, split hi/lo, store ----
    const float inv0 = 1.0f / l0;
    const float inv1 = 1.0f / l1;
    const size_t grow0 = qrow0 + wid * 16 + (lane >> 2);
#pragma unroll
    for (int nt = 0; nt < 8; nt++) {
        const int col = h * HD_ + nt * 8 + ccol;
        uint32_t h0, lo0, h1, lo1;
        pack_hilo(o[nt][0] * inv0, o[nt][1] * inv0, h0, lo0);
        pack_hilo(o[nt][2] * inv1, o[nt][3] * inv1, h1, lo1);
        *(uint32_t*)(outh + grow0 * D_ + col)       = h0;
        *(uint32_t*)(outl + grow0 * D_ + col)       = lo0;
        *(uint32_t*)(outh + (grow0 + 8) * D_ + col) = h1;
        *(uint32_t*)(outl + (grow0 + 8) * D_ + col) = lo1;
    }
}

// ----------------------------------------------------------------------------
// Launch
// ----------------------------------------------------------------------------
extern "C" void kernel_launch(void* const* d_in, const int* in_sizes, int n_in,
                              void* d_out, int out_size)
{
    const float* x     = (const float*)d_in[0];
    const float* Wqkv  = (const float*)d_in[1];
    const float* bqkv  = (const float*)d_in[2];
    const float* Wproj = (const float*)d_in[3];
    const float* bproj = (const float*)d_in[4];
    float* out = (float*)d_out;

    __nv_bfloat16 *xhi, *xlo, *qkvh, *qkvl, *ahi, *alo, *wqh, *wql, *wph, *wpl;
    cudaGetSymbolAddress((void**)&xhi, g_xhi);
    cudaGetSymbolAddress((void**)&xlo, g_xlo);
    cudaGetSymbolAddress((void**)&qkvh, g_qkvh);
    cudaGetSymbolAddress((void**)&qkvl, g_qkvl);
    cudaGetSymbolAddress((void**)&ahi, g_ahi);
    cudaGetSymbolAddress((void**)&alo, g_alo);
    cudaGetSymbolAddress((void**)&wqh, g_wqh);
    cudaGetSymbolAddress((void**)&wql, g_wql);
    cudaGetSymbolAddress((void**)&wph, g_wph);
    cudaGetSymbolAddress((void**)&wpl, g_wpl);

    static bool attr_set = false;
    if (!attr_set) {
        cudaFuncSetAttribute(gemm_mma_kernel<true>,
                             cudaFuncAttributeMaxDynamicSharedMemorySize,
                             (int)GM_SMEM);
        cudaFuncSetAttribute(gemm_mma_kernel<false>,
                             cudaFuncAttributeMaxDynamicSharedMemorySize,
                             (int)GM_SMEM);
        cudaFuncSetAttribute(attn_mma_kernel,
                             cudaFuncAttributeMaxDynamicSharedMemorySize,
                             (int)AT_SMEM);
        attr_set = true;
    }

    const int n4x = M_ * D_ / 4;

    // prep: splits
    split_a_kernel<<<(n4x + 255) / 256, 256>>>(x, xhi, xlo, n4x);
    split_wT_kernel<<<dim3(QKV_N / 32, D_ / 32), dim3(32, 8)>>>(Wqkv, wqh, wql, D_, QKV_N);
    split_wT_kernel<<<dim3(D_ / 32, D_ / 32), dim3(32, 8)>>>(Wproj, wph, wpl, D_, D_);

    // 1) QKV projection -> bf16 hi/lo directly
    gemm_mma_kernel<true><<<dim3(QKV_N / 128, M_ / 128), 256, GM_SMEM>>>(
        xhi, xlo, wqh, wql, bqkv, nullptr, qkvh, qkvl, QKV_N, D_);

    // 2) causal flash attention (tensor cores) -> bf16 hi/lo
    attn_mma_kernel<<<dim3(L_ / 128, H_, B_), 256, AT_SMEM>>>(qkvh, qkvl, ahi, alo);

    // 3) output projection -> fp32 out
    gemm_mma_kernel<false><<<dim3(D_ / 128, M_ / 128), 256, GM_SMEM>>>(
        ahi, alo, wph, wpl, bproj, out, nullptr, nullptr, D_, D_);
}

// round 16
// speedup vs baseline: 1.0350x; 1.0350x over previous
#include <cuda_runtime.h>
#include <cuda_bf16.h>
#include <math_constants.h>
#include <cstdint>

// Problem constants
constexpr int B_  = 4;
constexpr int L_  = 2048;
constexpr int D_  = 1024;
constexpr int H_  = 16;
constexpr int HD_ = 64;
constexpr int M_  = B_ * L_;       // 8192
constexpr int QKV_N = 3 * D_;      // 3072

// ---------------------------------------------------------------------------
// Scratch (allocation-free -> __device__ globals)
// ---------------------------------------------------------------------------
__device__ __nv_bfloat16 g_xhi[(size_t)M_ * D_];
__device__ __nv_bfloat16 g_xlo[(size_t)M_ * D_];
__device__ __nv_bfloat16 g_qkvh[(size_t)M_ * QKV_N];
__device__ __nv_bfloat16 g_qkvl[(size_t)M_ * QKV_N];
__device__ __nv_bfloat16 g_ahi[(size_t)M_ * D_];
__device__ __nv_bfloat16 g_alo[(size_t)M_ * D_];
__device__ __nv_bfloat16 g_wqh[(size_t)QKV_N * D_];
__device__ __nv_bfloat16 g_wql[(size_t)QKV_N * D_];
__device__ __nv_bfloat16 g_wph[(size_t)D_ * D_];
__device__ __nv_bfloat16 g_wpl[(size_t)D_ * D_];

// ---------------------------------------------------------------------------
// PTX helpers
// ---------------------------------------------------------------------------
__device__ __forceinline__ uint32_t smem_u32(const void* p) {
    uint32_t a;
    asm("{ .reg .u64 t; cvta.to.shared.u64 t, %1; cvt.u32.u64 %0, t; }"
        : "=r"(a) : "l"(p));
    return a;
}
__device__ __forceinline__ void cpasync16(uint32_t saddr, const void* g) {
    asm volatile("cp.async.cg.shared.global [%0], [%1], 16;" :: "r"(saddr), "l"(g));
}
#define CP_COMMIT() asm volatile("cp.async.commit_group;" ::: "memory")
#define CP_WAIT(n)  asm volatile("cp.async.wait_group %0;" :: "n"(n) : "memory")

__device__ __forceinline__ void ldm_x4(uint32_t* r, uint32_t addr) {
    asm volatile("ldmatrix.sync.aligned.m8n8.x4.shared.b16 {%0,%1,%2,%3}, [%4];"
                 : "=r"(r[0]), "=r"(r[1]), "=r"(r[2]), "=r"(r[3]) : "r"(addr));
}
__device__ __forceinline__ void ldm_x4_t(uint32_t* r, uint32_t addr) {
    asm volatile("ldmatrix.sync.aligned.m8n8.x4.trans.shared.b16 {%0,%1,%2,%3}, [%4];"
                 : "=r"(r[0]), "=r"(r[1]), "=r"(r[2]), "=r"(r[3]) : "r"(addr));
}
__device__ __forceinline__ void mma_bf16(float* c, const uint32_t* a,
                                         const uint32_t* b) {
    asm("mma.sync.aligned.m16n8k16.row.col.f32.bf16.bf16.f32 "
        "{%0,%1,%2,%3},{%4,%5,%6,%7},{%8,%9},{%0,%1,%2,%3};"
        : "+f"(c[0]), "+f"(c[1]), "+f"(c[2]), "+f"(c[3])
        : "r"(a[0]), "r"(a[1]), "r"(a[2]), "r"(a[3]), "r"(b[0]), "r"(b[1]));
}
__device__ __forceinline__ void pack_hilo(float x, float y,
                                          uint32_t& hi, uint32_t& lo) {
    __nv_bfloat162 h2 = __floats2bfloat162_rn(x, y);
    float2 f2 = __bfloat1622float2(h2);
    __nv_bfloat162 l2 = __floats2bfloat162_rn(x - f2.x, y - f2.y);
    hi = *(uint32_t*)&h2;
    lo = *(uint32_t*)&l2;
}

// ---------------------------------------------------------------------------
// Split kernels
// ---------------------------------------------------------------------------
__global__ void split_a_kernel(const float* __restrict__ A,
                               __nv_bfloat16* __restrict__ Ah,
                               __nv_bfloat16* __restrict__ Al, int n4)
{
    int i = blockIdx.x * blockDim.x + threadIdx.x;
    if (i >= n4) return;
    float4 v = ((const float4*)A)[i];
    uint32_t h0, l0, h1, l1;
    pack_hilo(v.x, v.y, h0, l0);
    pack_hilo(v.z, v.w, h1, l1);
    ((uint32_t*)Ah)[2 * i]     = h0;
    ((uint32_t*)Ah)[2 * i + 1] = h1;
    ((uint32_t*)Al)[2 * i]     = l0;
    ((uint32_t*)Al)[2 * i + 1] = l1;
}

__global__ void split_wT_kernel(const float* __restrict__ W,
                                __nv_bfloat16* __restrict__ Bh,
                                __nv_bfloat16* __restrict__ Bl, int K, int N)
{
    __shared__ float t[32][33];
    const int bx = blockIdx.x, by = blockIdx.y;
    const int tx = threadIdx.x, ty = threadIdx.y;
#pragma unroll
    for (int i = 0; i < 4; i++) {
        int k = by * 32 + ty + i * 8;
        t[ty + i * 8][tx] = W[(size_t)k * N + bx * 32 + tx];
    }
    __syncthreads();
#pragma unroll
    for (int i = 0; i < 4; i++) {
        int n = bx * 32 + ty + i * 8;
        int k = by * 32 + tx;
        float v = t[tx][ty + i * 8];
        __nv_bfloat16 h = __float2bfloat16_rn(v);
        Bh[(size_t)n * K + k] = h;
        Bl[(size_t)n * K + k] = __float2bfloat16_rn(v - __bfloat162float(h));
    }
}

// ---------------------------------------------------------------------------
// HMMA split-bf16 GEMM (unchanged proven state: 2 CTAs/SM, 3-stage pipeline,
// one barrier per chunk, intra-warp fragment pipeline, spread cp.async).
// ---------------------------------------------------------------------------
constexpr int GBH = 128 * 80;
constexpr int GBL = 128 * 64;
constexpr int GSTAGE = 2 * GBH + 2 * GBL;  // 36864
constexpr size_t GM_SMEM = 3 * GSTAGE;     // 110592 B

template <bool SPLIT_OUT>
__global__ void __launch_bounds__(256, 2) gemm_mma_kernel(
    const __nv_bfloat16* __restrict__ Ah, const __nv_bfloat16* __restrict__ Al,
    const __nv_bfloat16* __restrict__ Bh, const __nv_bfloat16* __restrict__ Bl,
    const float* __restrict__ bias, float* __restrict__ C,
    __nv_bfloat16* __restrict__ Ch, __nv_bfloat16* __restrict__ Cl,
    int N, int K)
{
    extern __shared__ char smem[];
    const uint32_t sb = smem_u32(smem);
    const int tid  = threadIdx.x;
    const int wid  = tid >> 5;
    const int lane = tid & 31;
    const int warp_m = wid >> 2;
    const int warp_n = wid & 3;
    const int row0 = blockIdx.y * 128;
    const int col0 = blockIdx.x * 128;

    float acc[4][4][4];
#pragma unroll
    for (int mt = 0; mt < 4; mt++)
#pragma unroll
        for (int nt = 0; nt < 4; nt++)
#pragma unroll
            for (int q = 0; q < 4; q++) acc[mt][nt][q] = 0.f;

    const int nChunks = K >> 5;
    const int lr0 = tid >> 2;
    const int lch = tid & 3;

    auto load_stage = [&](int s, int c) {
        const int k0 = c << 5;
        const uint32_t st = sb + s * GSTAGE;
#pragma unroll
        for (int i = 0; i < 2; i++) {
            const int r = lr0 + i * 64;
            const uint32_t so_h = r * 80 + lch * 16;
            const uint32_t so_l = r * 64 + ((lch ^ ((r >> 1) & 3)) << 4);
            const size_t ga = (size_t)(row0 + r) * K + k0 + lch * 8;
            const size_t gb = (size_t)(col0 + r) * K + k0 + lch * 8;
            cpasync16(st + so_h, Ah + ga);
            cpasync16(st + GBH + so_h, Bh + gb);
            cpasync16(st + 2 * GBH + so_l, Al + ga);
            cpasync16(st + 2 * GBH + GBL + so_l, Bl + gb);
        }
    };
    auto load_slot = [&](int s, int c2, int slot) {
        const int k0 = c2 << 5;
        const uint32_t st = sb + s * GSTAGE;
        const int i = slot >> 2;
        const int which = slot & 3;
        const int r = lr0 + i * 64;
        const uint32_t so_h = r * 80 + lch * 16;
        const uint32_t so_l = r * 64 + ((lch ^ ((r >> 1) & 3)) << 4);
        if (which == 0)
            cpasync16(st + so_h, Ah + (size_t)(row0 + r) * K + k0 + lch * 8);
        else if (which == 1)
            cpasync16(st + GBH + so_h, Bh + (size_t)(col0 + r) * K + k0 + lch * 8);
        else if (which == 2)
            cpasync16(st + 2 * GBH + so_l, Al + (size_t)(row0 + r) * K + k0 + lch * 8);
        else
            cpasync16(st + 2 * GBH + GBL + so_l,
                      Bl + (size_t)(col0 + r) * K + k0 + lch * 8);
    };

    load_stage(0, 0);
    CP_COMMIT();
    load_stage(1, 1);
    CP_COMMIT();

    const int arow  = warp_m * 64 + (lane & 15);
    const int acolb = ((lane >> 4) & 1) * 16;
    const int ahalf = (lane >> 4) & 1;
    const int bnrow = warp_n * 32 + (lane & 7) + ((lane >> 4) & 1) * 8;
    const int bcolb = ((lane >> 3) & 1) * 16;
    const int bhalf = (lane >> 3) & 1;

    int cur = 0, ldb = 2;
    for (int c = 0; c < nChunks; c++) {
        if (c + 1 < nChunks) { CP_WAIT(1); } else { CP_WAIT(0); }
        __syncthreads();
        const bool doLoad = (c + 2 < nChunks);

        const uint32_t st  = sb + cur * GSTAGE;
        const uint32_t sAh = st;
        const uint32_t sBh = st + GBH;
        const uint32_t sAl = st + 2 * GBH;
        const uint32_t sBl = st + 2 * GBH + GBL;

        auto ldA = [&](uint32_t* h, uint32_t* l, int ks, int mt) {
            const int rA = arow + mt * 16;
            const uint32_t roh = (uint32_t)rA * 80 + acolb + ks * 32;
            const int cA = ks * 2 + ahalf;
            const uint32_t rol = (uint32_t)rA * 64 +
                                 ((cA ^ ((rA >> 1) & 3)) << 4);
            ldm_x4(h, sAh + roh);
            ldm_x4(l, sAl + rol);
        };

        uint32_t aH[2][4], aL[2][4];
        ldA(aH[0], aL[0], 0, 0);

#pragma unroll
        for (int ks = 0; ks < 2; ks++) {
            const int kb = ks * 32;
            uint32_t bh[4][2], bl[4][2];
#pragma unroll
            for (int np = 0; np < 2; np++) {
                const int rB = bnrow + np * 16;
                const uint32_t roh = (uint32_t)rB * 80 + bcolb + kb;
                const int cB = ks * 2 + bhalf;
                const uint32_t rol = (uint32_t)rB * 64 +
                                     ((cB ^ ((rB >> 1) & 3)) << 4);
                uint32_t t0[4], t1[4];
                ldm_x4(t0, sBh + roh);
                ldm_x4(t1, sBl + rol);
                bh[2 * np][0] = t0[0]; bh[2 * np][1] = t0[1];
                bh[2 * np + 1][0] = t0[2]; bh[2 * np + 1][1] = t0[3];
                bl[2 * np][0] = t1[0]; bl[2 * np][1] = t1[1];
                bl[2 * np + 1][0] = t1[2]; bl[2 * np + 1][1] = t1[3];
            }
#pragma unroll
            for (int mt = 0; mt < 4; mt++) {
                const int slot = ks * 4 + mt;
                if (doLoad) load_slot(ldb, c + 2, slot);
                if (slot < 7) {
                    const int ns = slot + 1;
                    ldA(aH[ns & 1], aL[ns & 1], ns >> 2, ns & 3);
                }
                const uint32_t* ah = aH[slot & 1];
                const uint32_t* al = aL[slot & 1];
#pragma unroll
                for (int nt = 0; nt < 4; nt++)
                    mma_bf16(acc[mt][nt], ah, bh[nt]);
#pragma unroll
                for (int nt = 0; nt < 4; nt++)
                    mma_bf16(acc[mt][nt], ah, bl[nt]);
#pragma unroll
                for (int nt = 0; nt < 4; nt++)
                    mma_bf16(acc[mt][nt], al, bh[nt]);
            }
        }
        if (doLoad) CP_COMMIT();
        cur = (cur == 2) ? 0 : cur + 1;
        ldb = (ldb == 2) ? 0 : ldb + 1;
    }

    const int g  = lane >> 2;
    const int tc = (lane & 3) * 2;
#pragma unroll
    for (int nt = 0; nt < 4; nt++) {
        const int cg = col0 + warp_n * 32 + nt * 8 + tc;
        const float bx = bias[cg];
        const float by = bias[cg + 1];
#pragma unroll
        for (int mt = 0; mt < 4; mt++) {
            const int rg = row0 + warp_m * 64 + mt * 16 + g;
            float v00 = acc[mt][nt][0] + bx, v01 = acc[mt][nt][1] + by;
            float v10 = acc[mt][nt][2] + bx, v11 = acc[mt][nt][3] + by;
            if (SPLIT_OUT) {
                uint32_t h0, l0, h1, l1;
                pack_hilo(v00, v01, h0, l0);
                pack_hilo(v10, v11, h1, l1);
                *(uint32_t*)(Ch + (size_t)rg * N + cg)       = h0;
                *(uint32_t*)(Cl + (size_t)rg * N + cg)       = l0;
                *(uint32_t*)(Ch + (size_t)(rg + 8) * N + cg) = h1;
                *(uint32_t*)(Cl + (size_t)(rg + 8) * N + cg) = l1;
            } else {
                float2 a0; a0.x = v00; a0.y = v01;
                float2 a1; a1.x = v10; a1.y = v11;
                *(float2*)(C + (size_t)rg * N + cg)       = a0;
                *(float2*)(C + (size_t)(rg + 8) * N + cg) = a1;
            }
        }
    }
}

// ---------------------------------------------------------------------------
// Tensor-core flash attention (causal). CTA = 128 q-rows x (b,h). 8 warps.
// R13 proven structure (3-stage K/V, 1 barrier/tile, LPT, spread loads,
// slot-pipelined fragments). R15: softmax computed in the s*(SCALE*LOG2E)
// domain — removes the LOG2E multiply from every exp2f argument.
// ---------------------------------------------------------------------------
constexpr int APB      = 144;
constexpr int AT_QB    = 128 * APB;         // 18432
constexpr int AT_KVT   = 64 * APB;          // 9216
constexpr int AT_STAGE = 4 * AT_KVT;        // 36864
constexpr size_t AT_SMEM = 2 * (size_t)AT_QB + 3 * (size_t)AT_STAGE;  // 147456

__global__ void __launch_bounds__(256, 1) attn_mma_kernel(
    const __nv_bfloat16* __restrict__ qkvh,
    const __nv_bfloat16* __restrict__ qkvl,
    __nv_bfloat16* __restrict__ outh,
    __nv_bfloat16* __restrict__ outl)
{
    extern __shared__ char smem[];
    const uint32_t sb = smem_u32(smem);
    const uint32_t sQh = sb;
    const uint32_t sQl = sb + AT_QB;
    const uint32_t sS0 = sb + 2 * AT_QB;

    const int qb = (int)gridDim.x - 1 - (int)blockIdx.x;  // LPT: heavy first
    const int h  = blockIdx.y;
    const int b  = blockIdx.z;
    const int tid  = threadIdx.x;
    const int wid  = tid >> 5;
    const int lane = tid & 31;

    const size_t qrow0 = (size_t)(b * L_ + qb * 128);

    // ---- Q hi/lo -> smem ----
#pragma unroll
    for (int i = 0; i < 4; i++) {
        const int id = i * 256 + tid;
        const int r = id >> 3, s = id & 7;
        const size_t g = (qrow0 + r) * QKV_N + h * HD_ + s * 8;
        const uint32_t so = r * APB + s * 16;
        cpasync16(sQh + so, qkvh + g);
        cpasync16(sQl + so, qkvl + g);
    }
    CP_COMMIT();

    const int nkt = 2 * qb + 2;

    auto load_kv = [&](int buf, int kt) {
        const uint32_t st = sS0 + buf * AT_STAGE;
        const size_t krow0 = (size_t)(b * L_ + kt * 64);
#pragma unroll
        for (int i = 0; i < 2; i++) {
            const int id = i * 256 + tid;
            const int r = id >> 3, s = id & 7;
            const size_t gk = (krow0 + r) * QKV_N + D_ + h * HD_ + s * 8;
            const size_t gv = gk + D_;
            const uint32_t so = r * APB + s * 16;
            cpasync16(st + 0 * AT_KVT + so, qkvh + gk);
            cpasync16(st + 1 * AT_KVT + so, qkvl + gk);
            cpasync16(st + 2 * AT_KVT + so, qkvh + gv);
            cpasync16(st + 3 * AT_KVT + so, qkvl + gv);
        }
    };
    auto load_kv_slot = [&](int buf, int kt, int slot) {
        const uint32_t st = sS0 + buf * AT_STAGE;
        const size_t krow0 = (size_t)(b * L_ + kt * 64);
        const int i = slot >> 2;
        const int which = slot & 3;
        const int id = i * 256 + tid;
        const int r = id >> 3, s = id & 7;
        const size_t gk = (krow0 + r) * QKV_N + D_ + h * HD_ + s * 8;
        const uint32_t so = r * APB + s * 16;
        if (which == 0)      cpasync16(st + 0 * AT_KVT + so, qkvh + gk);
        else if (which == 1) cpasync16(st + 1 * AT_KVT + so, qkvl + gk);
        else if (which == 2) cpasync16(st + 2 * AT_KVT + so, qkvh + gk + D_);
        else                 cpasync16(st + 3 * AT_KVT + so, qkvl + gk + D_);
    };

    load_kv(0, 0);
    CP_COMMIT();
    load_kv(1, 1);
    CP_COMMIT();

    CP_WAIT(2);
    __syncthreads();
    uint32_t qh[4][4], ql[4][4];
    {
        const uint32_t base = (uint32_t)(wid * 16 + (lane & 15)) * APB +
                              ((lane >> 4) & 1) * 16;
#pragma unroll
        for (int j = 0; j < 4; j++) {
            ldm_x4(qh[j], sQh + base + j * 32);
            ldm_x4(ql[j], sQl + base + j * 32);
        }
    }

    float o[8][4];
#pragma unroll
    for (int nt = 0; nt < 8; nt++)
#pragma unroll
        for (int q = 0; q < 4; q++) o[nt][q] = 0.f;
    float m0 = -CUDART_INF_F, m1 = -CUDART_INF_F;
    float l0 = 0.f, l1 = 0.f;

    const int row_r0 = qb * 128 + wid * 16 + (lane >> 2);
    const int ccol   = 2 * (lane & 3);
    // fold: work in s * (SCALE*LOG2E) domain -> exp2f args need no multiply
    constexpr float SL = 0.125f * 1.44269504f;

    const uint32_t kbase = (uint32_t)((lane & 7) + ((lane >> 4) & 1) * 8) * APB +
                           ((lane >> 3) & 1) * 16;
    const int vmat = lane >> 3;
    const uint32_t vrowb = (uint32_t)((vmat & 1) * 8 + (lane & 7)) * APB +
                           (vmat >> 1) * 16;

    int cur = 0, ldb = 2;
    for (int kt = 0; kt < nkt; kt++) {
        if (kt + 1 < nkt) { CP_WAIT(1); } else { CP_WAIT(0); }
        __syncthreads();
        const bool doLoad = (kt + 2 < nkt);

        const uint32_t st  = sS0 + cur * AT_STAGE;
        const uint32_t sKh = st;
        const uint32_t sKl = st + AT_KVT;
        const uint32_t sVh = st + 2 * AT_KVT;
        const uint32_t sVl = st + 3 * AT_KVT;

        // ---- S = Q K^T (slot-pipelined; spread cp.async over slots 0..7) ----
        float s[8][4];
#pragma unroll
        for (int nt = 0; nt < 8; nt++)
#pragma unroll
            for (int q = 0; q < 4; q++) s[nt][q] = 0.f;

        uint32_t kfh[2][2][2], kfl[2][2][2];
        auto ldK = [&](int buf, int j, int np) {
            const uint32_t ro = kbase + (uint32_t)(np * 16) * APB + j * 32;
            uint32_t t0[4], t1[4];
            ldm_x4(t0, sKh + ro);
            ldm_x4(t1, sKl + ro);
            kfh[buf][0][0] = t0[0]; kfh[buf][0][1] = t0[1];
            kfh[buf][1][0] = t0[2]; kfh[buf][1][1] = t0[3];
            kfl[buf][0][0] = t1[0]; kfl[buf][0][1] = t1[1];
            kfl[buf][1][0] = t1[2]; kfl[buf][1][1] = t1[3];
        };
        ldK(0, 0, 0);
#pragma unroll
        for (int j = 0; j < 4; j++) {
#pragma unroll
            for (int np = 0; np < 4; np++) {
                const int slot = j * 4 + np;
                const int cb = slot & 1;
                if (doLoad && slot < 8) load_kv_slot(ldb, kt + 2, slot);
                if (slot < 15) ldK(cb ^ 1, (slot + 1) >> 2, (slot + 1) & 3);
#pragma unroll
                for (int t = 0; t < 2; t++) {
                    const int nt = 2 * np + t;
                    mma_bf16(s[nt], qh[j], kfh[cb][t]);
                    mma_bf16(s[nt], qh[j], kfl[cb][t]);
                    mma_bf16(s[nt], ql[j], kfh[cb][t]);
                }
            }
        }
        if (doLoad) CP_COMMIT();

        // ---- scale into log2 domain + causal mask ----
#pragma unroll
        for (int nt = 0; nt < 8; nt++)
#pragma unroll
            for (int q = 0; q < 4; q++) s[nt][q] *= SL;

        if (kt >= 2 * qb) {
#pragma unroll
            for (int nt = 0; nt < 8; nt++) {
                const int col = kt * 64 + nt * 8 + ccol;
                if (col > row_r0)         s[nt][0] = -CUDART_INF_F;
                if (col + 1 > row_r0)     s[nt][1] = -CUDART_INF_F;
                if (col > row_r0 + 8)     s[nt][2] = -CUDART_INF_F;
                if (col + 1 > row_r0 + 8) s[nt][3] = -CUDART_INF_F;
            }
        }

        // ---- online softmax (log2 domain: no LOG2E multiply in exps) ----
        float tm0 = -CUDART_INF_F, tm1 = -CUDART_INF_F;
#pragma unroll
        for (int nt = 0; nt < 8; nt++) {
            tm0 = fmaxf(tm0, fmaxf(s[nt][0], s[nt][1]));
            tm1 = fmaxf(tm1, fmaxf(s[nt][2], s[nt][3]));
        }
        tm0 = fmaxf(tm0, __shfl_xor_sync(0xffffffffu, tm0, 1));
        tm0 = fmaxf(tm0, __shfl_xor_sync(0xffffffffu, tm0, 2));
        tm1 = fmaxf(tm1, __shfl_xor_sync(0xffffffffu, tm1, 1));
        tm1 = fmaxf(tm1, __shfl_xor_sync(0xffffffffu, tm1, 2));

        const float mn0 = fmaxf(m0, tm0);
        const float mn1 = fmaxf(m1, tm1);
        const float a0 = exp2f(m0 - mn0);
        const float a1 = exp2f(m1 - mn1);
        m0 = mn0; m1 = mn1;

        float rs0 = 0.f, rs1 = 0.f;
#pragma unroll
        for (int nt = 0; nt < 8; nt++) {
            float p0 = exp2f(s[nt][0] - mn0);
            float p1 = exp2f(s[nt][1] - mn0);
            float p2 = exp2f(s[nt][2] - mn1);
            float p3 = exp2f(s[nt][3] - mn1);
            s[nt][0] = p0; s[nt][1] = p1; s[nt][2] = p2; s[nt][3] = p3;
            rs0 += p0 + p1;
            rs1 += p2 + p3;
        }
        rs0 += __shfl_xor_sync(0xffffffffu, rs0, 1);
        rs0 += __shfl_xor_sync(0xffffffffu, rs0, 2);
        rs1 += __shfl_xor_sync(0xffffffffu, rs1, 1);
        rs1 += __shfl_xor_sync(0xffffffffu, rs1, 2);
        l0 = a0 * l0 + rs0;
        l1 = a1 * l1 + rs1;

#pragma unroll
        for (int nt = 0; nt < 8; nt++) {
            o[nt][0] *= a0; o[nt][1] *= a0;
            o[nt][2] *= a1; o[nt][3] *= a1;
        }

        // ---- V fragment pipeline setup: first load hides under P pack ----
        uint32_t vfh[2][2][2], vfl[2][2][2];
        auto ldV = [&](int buf, int j, int pp) {
            const uint32_t ro = vrowb + (uint32_t)(j * 16) * APB + pp * 32;
            uint32_t t0[4], t1[4];
            ldm_x4_t(t0, sVh + ro);
            ldm_x4_t(t1, sVl + ro);
            vfh[buf][0][0] = t0[0]; vfh[buf][0][1] = t0[1];
            vfh[buf][1][0] = t0[2]; vfh[buf][1][1] = t0[3];
            vfl[buf][0][0] = t1[0]; vfl[buf][0][1] = t1[1];
            vfl[buf][1][0] = t1[2]; vfl[buf][1][1] = t1[3];
        };
        ldV(0, 0, 0);

        // ---- pack P (C-frag -> A-frag identity) ----
        uint32_t ph[4][4], pl[4][4];
#pragma unroll
        for (int j = 0; j < 4; j++) {
            pack_hilo(s[2 * j][0],     s[2 * j][1],     ph[j][0], pl[j][0]);
            pack_hilo(s[2 * j][2],     s[2 * j][3],     ph[j][1], pl[j][1]);
            pack_hilo(s[2 * j + 1][0], s[2 * j + 1][1], ph[j][2], pl[j][2]);
            pack_hilo(s[2 * j + 1][2], s[2 * j + 1][3], ph[j][3], pl[j][3]);
        }

        // ---- O += P V (3 split passes, slot-pipelined fragments) ----
#pragma unroll
        for (int j = 0; j < 4; j++) {
#pragma unroll
            for (int pp = 0; pp < 4; pp++) {
                const int slot = j * 4 + pp;
                const int cb = slot & 1;
                if (slot < 15) ldV(cb ^ 1, (slot + 1) >> 2, (slot + 1) & 3);
#pragma unroll
                for (int t = 0; t < 2; t++) {
                    const int nt = 2 * pp + t;
                    mma_bf16(o[nt], ph[j], vfh[cb][t]);
                    mma_bf16(o[nt], ph[j], vfl[cb][t]);
                    mma_bf16(o[nt], pl[j], vfh[cb][t]);
                }
            }
        }
        cur = (cur == 2) ? 0 : cur + 1;
        ldb = (ldb == 2) ? 0 : ldb + 1;
    }

    // ---- finalize: /l, split hi/lo, store ----
    const float inv0 = 1.0f / l0;
    const float inv1 = 1.0f / l1;
    const size_t grow0 = qrow0 + wid * 16 + (lane >> 2);
#pragma unroll
    for (int nt = 0; nt < 8; nt++) {
        const int col = h * HD_ + nt * 8 + ccol;
        uint32_t h0, lo0, h1, lo1;
        pack_hilo(o[nt][0] * inv0, o[nt][1] * inv0, h0, lo0);
        pack_hilo(o[nt][2] * inv1, o[nt][3] * inv1, h1, lo1);
        *(uint32_t*)(outh + grow0 * D_ + col)       = h0;
        *(uint32_t*)(outl + grow0 * D_ + col)       = lo0;
        *(uint32_t*)(outh + (grow0 + 8) * D_ + col) = h1;
        *(uint32_t*)(outl + (grow0 + 8) * D_ + col) = lo1;
    }
}

// ----------------------------------------------------------------------------
// Launch
// ----------------------------------------------------------------------------
extern "C" void kernel_launch(void* const* d_in, const int* in_sizes, int n_in,
                              void* d_out, int out_size)
{
    const float* x     = (const float*)d_in[0];
    const float* Wqkv  = (const float*)d_in[1];
    const float* bqkv  = (const float*)d_in[2];
    const float* Wproj = (const float*)d_in[3];
    const float* bproj = (const float*)d_in[4];
    float* out = (float*)d_out;

    __nv_bfloat16 *xhi, *xlo, *qkvh, *qkvl, *ahi, *alo, *wqh, *wql, *wph, *wpl;
    cudaGetSymbolAddress((void**)&xhi, g_xhi);
    cudaGetSymbolAddress((void**)&xlo, g_xlo);
    cudaGetSymbolAddress((void**)&qkvh, g_qkvh);
    cudaGetSymbolAddress((void**)&qkvl, g_qkvl);
    cudaGetSymbolAddress((void**)&ahi, g_ahi);
    cudaGetSymbolAddress((void**)&alo, g_alo);
    cudaGetSymbolAddress((void**)&wqh, g_wqh);
    cudaGetSymbolAddress((void**)&wql, g_wql);
    cudaGetSymbolAddress((void**)&wph, g_wph);
    cudaGetSymbolAddress((void**)&wpl, g_wpl);

    static bool attr_set = false;
    if (!attr_set) {
        cudaFuncSetAttribute(gemm_mma_kernel<true>,
                             cudaFuncAttributeMaxDynamicSharedMemorySize,
                             (int)GM_SMEM);
        cudaFuncSetAttribute(gemm_mma_kernel<false>,
                             cudaFuncAttributeMaxDynamicSharedMemorySize,
                             (int)GM_SMEM);
        cudaFuncSetAttribute(attn_mma_kernel,
                             cudaFuncAttributeMaxDynamicSharedMemorySize,
                             (int)AT_SMEM);
        attr_set = true;
    }

    const int n4x = M_ * D_ / 4;

    // prep: splits
    split_a_kernel<<<(n4x + 255) / 256, 256>>>(x, xhi, xlo, n4x);
    split_wT_kernel<<<dim3(QKV_N / 32, D_ / 32), dim3(32, 8)>>>(Wqkv, wqh, wql, D_, QKV_N);
    split_wT_kernel<<<dim3(D_ / 32, D_ / 32), dim3(32, 8)>>>(Wproj, wph, wpl, D_, D_);

    // 1) QKV projection -> bf16 hi/lo directly
    gemm_mma_kernel<true><<<dim3(QKV_N / 128, M_ / 128), 256, GM_SMEM>>>(
        xhi, xlo, wqh, wql, bqkv, nullptr, qkvh, qkvl, QKV_N, D_);

    // 2) causal flash attention (tensor cores) -> bf16 hi/lo
    attn_mma_kernel<<<dim3(L_ / 128, H_, B_), 256, AT_SMEM>>>(qkvh, qkvl, ahi, alo);

    // 3) output projection -> fp32 out
    gemm_mma_kernel<false><<<dim3(D_ / 128, M_ / 128), 256, GM_SMEM>>>(
        ahi, alo, wph, wpl, bproj, out, nullptr, nullptr, D_, D_);
}